// round 5
// baseline (speedup 1.0000x reference)
#include <cuda_runtime.h>
#include <cuda_bf16.h>
#include <cstdint>
#include <math.h>

// Problem constants
#define B    4096
#define NF   64
#define KB   48
#define DE   64
#define F    4096
#define E    8
#define H    1024
#define O    512
#define T    2
#define TH   256

// ---------------- low-level helpers (plain sm_80+ PTX only) ----------------
__device__ __forceinline__ uint32_t smem_to_u32(const void* p) {
    uint32_t a;
    asm("{ .reg .u64 t; cvta.to.shared.u64 t, %1; cvt.u32.u64 %0, t; }" : "=r"(a) : "l"(p));
    return a;
}
__device__ __forceinline__ void cp_async16(uint32_t dst, const void* src, int src_bytes) {
    asm volatile("cp.async.cg.shared.global [%0], [%1], 16, %2;"
                 :: "r"(dst), "l"(src), "r"(src_bytes) : "memory");
}
#define CP_COMMIT() asm volatile("cp.async.commit_group;" ::: "memory")
#define CP_WAIT(n)  asm volatile("cp.async.wait_group %0;" :: "n"(n) : "memory")

__device__ __forceinline__ void ldsm_x4(uint32_t* r, uint32_t addr) {
    asm volatile("ldmatrix.sync.aligned.m8n8.x4.shared.b16 {%0,%1,%2,%3}, [%4];"
                 : "=r"(r[0]), "=r"(r[1]), "=r"(r[2]), "=r"(r[3]) : "r"(addr));
}
__device__ __forceinline__ void mma_bf16(float* c, const uint32_t* a, const uint32_t* b) {
    asm volatile(
        "mma.sync.aligned.m16n8k16.row.col.f32.bf16.bf16.f32 "
        "{%0,%1,%2,%3}, {%4,%5,%6,%7}, {%8,%9}, {%0,%1,%2,%3};"
        : "+f"(c[0]), "+f"(c[1]), "+f"(c[2]), "+f"(c[3])
        : "r"(a[0]), "r"(a[1]), "r"(a[2]), "r"(a[3]), "r"(b[0]), "r"(b[1]));
}

// ---------------- device scratch ----------------
__device__ __nv_bfloat16 g_flat_hi[(size_t)B * F];     // 32 MB
__device__ __nv_bfloat16 g_flat_lo[(size_t)B * F];     // 32 MB
__device__ __nv_bfloat16 g_w1t_hi[(size_t)E * H * F];  // 64 MB  [e][h][f]
__device__ __nv_bfloat16 g_w1t_lo[(size_t)E * H * F];  // 64 MB
__device__ __nv_bfloat16 g_w2t_hi[(size_t)E * O * H];  // 8 MB   [e][o][h]
__device__ __nv_bfloat16 g_w2t_lo[(size_t)E * O * H];  // 8 MB
__device__ __nv_bfloat16 g_h_hi[(size_t)2 * B * H];    // 16 MB
__device__ __nv_bfloat16 g_h_lo[(size_t)2 * B * H];    // 16 MB
__device__ float g_eo[(size_t)2 * B * O];              // 16 MB
__device__ int   g_count[E];
__device__ int   g_base[E];
__device__ int   g_cursor[E];
__device__ int   g_te[B * 2];
__device__ float g_tg[B * 2];
__device__ int   g_rows[2 * B];
__device__ float g_gates[2 * B];
__device__ int   g_pair[B * 2];

// ---------------- init ----------------
__global__ void k_init() {
    if (threadIdx.x < E) g_count[threadIdx.x] = 0;
}

// ---------------- weight split + transpose: W[e][k][n] -> T[e][n][k] bf16 hi/lo ----------------
__global__ __launch_bounds__(256) void k_wsplit(
    const float* __restrict__ W, __nv_bfloat16* __restrict__ Thi,
    __nv_bfloat16* __restrict__ Tlo, int Kdim, int Ndim)
{
    __shared__ float t[32][33];
    int e = blockIdx.z;
    int kb = blockIdx.y * 32;
    int nb = blockIdx.x * 32;
    int tx = threadIdx.x, ty = threadIdx.y;
    const float* Wb = W + (size_t)e * Kdim * Ndim;
    #pragma unroll
    for (int i = ty; i < 32; i += 8)
        t[i][tx] = Wb[(size_t)(kb + i) * Ndim + nb + tx];
    __syncthreads();
    #pragma unroll
    for (int i = ty; i < 32; i += 8) {
        float v = t[tx][i];
        __nv_bfloat16 h = __float2bfloat16(v);
        __nv_bfloat16 l = __float2bfloat16(v - __bfloat162float(h));
        size_t o = ((size_t)e * Ndim + nb + i) * Kdim + kb + tx;
        Thi[o] = h; Tlo[o] = l;
    }
}

// ---------------- PLE + embedding + ReLU -> flat hi/lo ----------------
// grid (NF, B/64), block 256. 64 rows per block; thread = (4 rows) x (4 d-cols).
__global__ __launch_bounds__(256) void k_ple(
    const float* __restrict__ x, const float* __restrict__ plew,
    const float* __restrict__ pleb, const float* __restrict__ embW,
    const float* __restrict__ embb)
{
    int n = blockIdx.x;
    int b0 = blockIdx.y * 64;
    int tid = threadIdx.x;

    __shared__ float Wsh[KB * DE];      // 12 KB
    __shared__ float wsh[KB], bsh[KB], ebias[DE];
    __shared__ float xs[64];
    __shared__ float enc_sh[64][KB];    // 12 KB (row stride 192B, 16B aligned)

    for (int i = tid; i < KB * DE; i += 256) Wsh[i] = embW[(size_t)n * KB * DE + i];
    if (tid < KB) { wsh[tid] = plew[n * KB + tid]; bsh[tid] = pleb[n * KB + tid]; }
    if (tid < DE) ebias[tid] = embb[n * DE + tid];
    if (tid < 64) xs[tid] = x[(b0 + tid) * NF + n];
    __syncthreads();

    // phase 1: encode 64 rows x 48 bins
    for (int idx = tid; idx < 64 * KB; idx += 256) {
        int bl = idx / KB, k = idx - bl * KB;
        float enc = bsh[k] + wsh[k] * xs[bl];
        if (k == 0)           enc = fminf(enc, 1.f);
        else if (k == KB - 1) enc = fmaxf(enc, 0.f);
        else                  enc = fminf(fmaxf(enc, 0.f), 1.f);
        enc_sh[bl][k] = enc;
    }
    __syncthreads();

    // phase 2: 48x64 matmul, thread = 4 rows x 4 cols
    int c0 = (tid & 15) * 4;
    int r0 = (tid >> 4) * 4;

    float acc[4][4];
    #pragma unroll
    for (int r = 0; r < 4; r++)
        #pragma unroll
        for (int j = 0; j < 4; j++) acc[r][j] = ebias[c0 + j];

    #pragma unroll
    for (int k4 = 0; k4 < KB; k4 += 4) {
        float4 wv[4];
        #pragma unroll
        for (int kk = 0; kk < 4; kk++)
            wv[kk] = *(const float4*)&Wsh[(k4 + kk) * DE + c0];
        #pragma unroll
        for (int r = 0; r < 4; r++) {
            float4 ev = *(const float4*)&enc_sh[r0 + r][k4];
            const float* w0 = (const float*)&wv[0];
            const float* w1 = (const float*)&wv[1];
            const float* w2 = (const float*)&wv[2];
            const float* w3 = (const float*)&wv[3];
            #pragma unroll
            for (int j = 0; j < 4; j++)
                acc[r][j] += ev.x * w0[j] + ev.y * w1[j] + ev.z * w2[j] + ev.w * w3[j];
        }
    }

    #pragma unroll
    for (int r = 0; r < 4; r++) {
        int b = b0 + r0 + r;
        uint32_t hw[2], lw[2];
        #pragma unroll
        for (int p = 0; p < 2; p++) {
            float v0 = fmaxf(acc[r][p * 2 + 0], 0.f);
            float v1 = fmaxf(acc[r][p * 2 + 1], 0.f);
            __nv_bfloat16 h0 = __float2bfloat16(v0);
            __nv_bfloat16 h1 = __float2bfloat16(v1);
            __nv_bfloat16 l0 = __float2bfloat16(v0 - __bfloat162float(h0));
            __nv_bfloat16 l1 = __float2bfloat16(v1 - __bfloat162float(h1));
            __nv_bfloat162 hh = __halves2bfloat162(h0, h1);
            __nv_bfloat162 ll = __halves2bfloat162(l0, l1);
            hw[p] = *(uint32_t*)&hh;
            lw[p] = *(uint32_t*)&ll;
        }
        size_t idx = (size_t)b * F + n * DE + c0;
        *(uint2*)&g_flat_hi[idx] = make_uint2(hw[0], hw[1]);
        *(uint2*)&g_flat_lo[idx] = make_uint2(lw[0], lw[1]);
    }
}

// ---------------- gate ----------------
__global__ __launch_bounds__(256) void k_gate(
    const float* __restrict__ gW, const float* __restrict__ gb)
{
    int b = blockIdx.x;
    int tid = threadIdx.x;
    int lane = tid & 31, wid = tid >> 5;

    float acc[E];
    #pragma unroll
    for (int e = 0; e < E; e++) acc[e] = 0.f;

    const __nv_bfloat16* xh = g_flat_hi + (size_t)b * F;
    const __nv_bfloat16* xl = g_flat_lo + (size_t)b * F;
    for (int f = tid; f < F; f += 256) {
        float xv = __bfloat162float(xh[f]) + __bfloat162float(xl[f]);
        #pragma unroll
        for (int e = 0; e < E; e++) acc[e] += xv * gW[f * E + e];
    }
    #pragma unroll
    for (int e = 0; e < E; e++)
        for (int off = 16; off; off >>= 1)
            acc[e] += __shfl_down_sync(0xffffffffu, acc[e], off);

    __shared__ float sb[E][8];
    __shared__ float slog[E];
    if (lane == 0) {
        #pragma unroll
        for (int e = 0; e < E; e++) sb[e][wid] = acc[e];
    }
    __syncthreads();
    if (tid < E) {
        float s = 0.f;
        #pragma unroll
        for (int w = 0; w < 8; w++) s += sb[tid][w];
        slog[tid] = s + gb[tid];
    }
    __syncthreads();
    if (tid == 0) {
        int i0 = 0;
        #pragma unroll
        for (int e = 1; e < E; e++) if (slog[e] > slog[i0]) i0 = e;
        int i1 = (i0 == 0) ? 1 : 0;
        #pragma unroll
        for (int e = 0; e < E; e++) if (e != i0 && slog[e] > slog[i1]) i1 = e;
        float e1 = __expf(slog[i1] - slog[i0]);
        float inv = 1.f / (1.f + e1);
        g_te[b * 2 + 0] = i0;  g_tg[b * 2 + 0] = inv;
        g_te[b * 2 + 1] = i1;  g_tg[b * 2 + 1] = e1 * inv;
        atomicAdd(&g_count[i0], 1);
        atomicAdd(&g_count[i1], 1);
    }
}

__global__ void k_scan() {
    if (threadIdx.x == 0) {
        int s = 0;
        for (int e = 0; e < E; e++) { g_base[e] = s; g_cursor[e] = s; s += g_count[e]; }
    }
}

__global__ __launch_bounds__(256) void k_assign() {
    int b = blockIdx.x * 256 + threadIdx.x;
    if (b >= B) return;
    #pragma unroll
    for (int j = 0; j < 2; j++) {
        int e = g_te[b * 2 + j];
        int slot = atomicAdd(&g_cursor[e], 1);
        g_rows[slot]  = b;
        g_gates[slot] = g_tg[b * 2 + j];
        g_pair[b * 2 + j] = slot;
    }
}

// ---------------- split-bf16 register-MMA expert GEMM ----------------
// CTA tile 256x128, 8 warps (4m x 2n), warp tile 64x64, k-tile 64, 2-stage cp.async.
#define GBM 256
#define GKT 64
#define STAGE_BYTES 98304
#define OFF_AHI 0
#define OFF_ALO 32768
#define OFF_BHI 65536
#define OFF_BLO 81920

template<int KTOT, int NTOT, int MODE>
__global__ __launch_bounds__(256, 1) void k_mma_gemm(
    const __nv_bfloat16* __restrict__ Ahi, const __nv_bfloat16* __restrict__ Alo,
    const __nv_bfloat16* __restrict__ Whi, const __nv_bfloat16* __restrict__ Wlo,
    const float* __restrict__ bias)
{
    int e = blockIdx.z;
    int cnt = g_count[e];
    int m0 = blockIdx.y * GBM;
    if (m0 >= cnt) return;
    int base = g_base[e];
    int n0 = blockIdx.x * 128;

    extern __shared__ char smem[];
    uint32_t sb = smem_to_u32(smem);
    __shared__ int rows_s[GBM];

    int tid = threadIdx.x;
    int lane = tid & 31, wid = tid >> 5;

    if (MODE == 0) {
        int m = m0 + tid;
        rows_s[tid] = (m < cnt) ? g_rows[base + m] : -1;
    }
    __syncthreads();

    // -------- loader setup --------
    // A: 256 rows, 1 thread per row, 8 chunks of 16B per plane
    int alrow = tid;
    uint32_t alsw = (uint32_t)((alrow & 7) << 4);
    uint32_t albase = (uint32_t)(alrow * 128);
    const __nv_bfloat16 *arow_hi, *arow_lo;
    int abytes;
    if (MODE == 0) {
        int gr = rows_s[alrow];
        abytes = (gr >= 0) ? 16 : 0;
        int r = (gr >= 0) ? gr : 0;
        arow_hi = Ahi + (size_t)r * KTOT;
        arow_lo = Alo + (size_t)r * KTOT;
    } else {
        int m = m0 + alrow;
        abytes = (m < cnt) ? 16 : 0;
        size_t r = (m < cnt) ? (size_t)(base + m) : 0;
        arow_hi = Ahi + r * KTOT;
        arow_lo = Alo + r * KTOT;
    }
    // B: 128 rows, 2 threads per row, 4 chunks each per plane
    int blrow = tid >> 1;
    int blcb  = (tid & 1) * 4;
    uint32_t blsw = (uint32_t)((blrow & 7) << 4);
    uint32_t blbase = (uint32_t)(blrow * 128);
    const __nv_bfloat16* brow_hi = Whi + ((size_t)e * NTOT + n0 + blrow) * KTOT;
    const __nv_bfloat16* brow_lo = Wlo + ((size_t)e * NTOT + n0 + blrow) * KTOT;

    // -------- mma setup: 8 warps = 4m x 2n, warp tile 64x64 --------
    int wm = wid >> 1;            // 0..3
    int wn = wid & 1;             // 0..1
    int a_row = wm * 64 + (lane & 15);
    uint32_t a_c  = (uint32_t)((lane >> 4) * 16);
    uint32_t asw  = (uint32_t)((a_row & 7) << 4);
    int b_row = wn * 64 + (lane & 7) + ((lane >> 4) << 3);
    uint32_t b_c  = (uint32_t)(((lane >> 3) & 1) * 16);
    uint32_t bsw  = (uint32_t)((b_row & 7) << 4);

    float acc[4][8][4];
    #pragma unroll
    for (int i = 0; i < 4; i++)
        #pragma unroll
        for (int j = 0; j < 8; j++)
            #pragma unroll
            for (int q = 0; q < 4; q++) acc[i][j][q] = 0.f;

    const int NT = KTOT / GKT;

    // prime stage 0
    {
        uint32_t s0 = sb;
        #pragma unroll
        for (int q = 0; q < 8; q++) {
            uint32_t so = albase + (((uint32_t)(q * 16)) ^ alsw);
            cp_async16(s0 + OFF_AHI + so, arow_hi + q * 8, abytes);
            cp_async16(s0 + OFF_ALO + so, arow_lo + q * 8, abytes);
        }
        #pragma unroll
        for (int q = 0; q < 4; q++) {
            int ch = blcb + q;
            uint32_t so = blbase + (((uint32_t)(ch * 16)) ^ blsw);
            cp_async16(s0 + OFF_BHI + so, brow_hi + ch * 8, 16);
            cp_async16(s0 + OFF_BLO + so, brow_lo + ch * 8, 16);
        }
        CP_COMMIT();
    }

    for (int kt = 0; kt < NT; kt++) {
        if (kt + 1 < NT) {
            uint32_t s1 = sb + ((kt + 1) & 1) * STAGE_BYTES;
            int k1 = (kt + 1) * GKT;
            #pragma unroll
            for (int q = 0; q < 8; q++) {
                uint32_t so = albase + (((uint32_t)(q * 16)) ^ alsw);
                cp_async16(s1 + OFF_AHI + so, arow_hi + k1 + q * 8, abytes);
                cp_async16(s1 + OFF_ALO + so, arow_lo + k1 + q * 8, abytes);
            }
            #pragma unroll
            for (int q = 0; q < 4; q++) {
                int ch = blcb + q;
                uint32_t so = blbase + (((uint32_t)(ch * 16)) ^ blsw);
                cp_async16(s1 + OFF_BHI + so, brow_hi + k1 + ch * 8, 16);
                cp_async16(s1 + OFF_BLO + so, brow_lo + k1 + ch * 8, 16);
            }
            CP_COMMIT();
            CP_WAIT(1);
        } else {
            CP_WAIT(0);
        }
        __syncthreads();

        uint32_t s0 = sb + (kt & 1) * STAGE_BYTES;
        #pragma unroll
        for (int kk = 0; kk < 4; kk++) {
            uint32_t ah[4][4], al[4][4], bh[4][4], bl[4][4];
            #pragma unroll
            for (int i = 0; i < 4; i++) {
                uint32_t ro = (uint32_t)((a_row + i * 16) * 128);
                uint32_t addr = s0 + OFF_AHI + ro + ((a_c + kk * 32) ^ asw);
                ldsm_x4(ah[i], addr);
                ldsm_x4(al[i], addr + (OFF_ALO - OFF_AHI));
            }
            #pragma unroll
            for (int p = 0; p < 4; p++) {
                uint32_t ro = (uint32_t)((b_row + p * 16) * 128);
                uint32_t addr = s0 + OFF_BHI + ro + ((b_c + kk * 32) ^ bsw);
                ldsm_x4(bh[p], addr);
                ldsm_x4(bl[p], addr + (OFF_BLO - OFF_BHI));
            }
            #pragma unroll
            for (int i = 0; i < 4; i++)
                #pragma unroll
                for (int j = 0; j < 8; j++) {
                    const uint32_t* bhj = &bh[j >> 1][(j & 1) * 2];
                    const uint32_t* blj = &bl[j >> 1][(j & 1) * 2];
                    mma_bf16(acc[i][j], ah[i], bhj);
                    mma_bf16(acc[i][j], ah[i], blj);
                    mma_bf16(acc[i][j], al[i], bhj);
                }
        }
        __syncthreads();
    }

    // -------- epilogue --------
    int g = lane >> 2;
    int cg = (lane & 3) * 2;
    #pragma unroll
    for (int i = 0; i < 4; i++) {
        #pragma unroll
        for (int half = 0; half < 2; half++) {
            int m = m0 + wm * 64 + i * 16 + g + half * 8;
            if (m < cnt) {
                int slot = base + m;
                float gate = (MODE == 1) ? g_gates[slot] : 0.f;
                #pragma unroll
                for (int j = 0; j < 8; j++) {
                    int col = n0 + wn * 64 + j * 8 + cg;
                    float bv0 = bias[(size_t)e * NTOT + col];
                    float bv1 = bias[(size_t)e * NTOT + col + 1];
                    float v0 = acc[i][j][half * 2 + 0] + bv0;
                    float v1 = acc[i][j][half * 2 + 1] + bv1;
                    if (MODE == 0) {
                        v0 = fmaxf(v0, 0.f); v1 = fmaxf(v1, 0.f);
                        __nv_bfloat16 h0 = __float2bfloat16(v0);
                        __nv_bfloat16 h1 = __float2bfloat16(v1);
                        __nv_bfloat16 l0 = __float2bfloat16(v0 - __bfloat162float(h0));
                        __nv_bfloat16 l1 = __float2bfloat16(v1 - __bfloat162float(h1));
                        __nv_bfloat162 hh = __halves2bfloat162(h0, h1);
                        __nv_bfloat162 ll = __halves2bfloat162(l0, l1);
                        *(uint32_t*)&g_h_hi[(size_t)slot * H + col] = *(uint32_t*)&hh;
                        *(uint32_t*)&g_h_lo[(size_t)slot * H + col] = *(uint32_t*)&ll;
                    } else {
                        float2 v = make_float2(gate * v0, gate * v1);
                        *(float2*)&g_eo[(size_t)slot * O + col] = v;
                    }
                }
            }
        }
    }
}

// ---------------- task towers ----------------
__global__ __launch_bounds__(256) void k_tower(
    const float* __restrict__ tw1, const float* __restrict__ tb1,
    const float* __restrict__ tw2, const float* __restrict__ tb2,
    float* __restrict__ out)
{
    int b0 = blockIdx.x * 16;
    int tid = threadIdx.x;
    int lane = tid & 31, wid = tid >> 5;

    __shared__ float moe_sh[16][O];
    __shared__ float sred[16][8];

    #pragma unroll
    for (int r = 0; r < 16; r++) {
        int b = b0 + r;
        int s0 = g_pair[b * 2 + 0], s1 = g_pair[b * 2 + 1];
        for (int c = tid; c < O; c += 256)
            moe_sh[r][c] = g_eo[(size_t)s0 * O + c] + g_eo[(size_t)s1 * O + c];
    }
    __syncthreads();

    for (int t = 0; t < T; t++) {
        float acc[16];
        #pragma unroll
        for (int r = 0; r < 16; r++) acc[r] = 0.f;

        const float* w1 = tw1 + (size_t)t * O * TH + tid;
        for (int o = 0; o < O; o++) {
            float w = w1[(size_t)o * TH];
            #pragma unroll
            for (int r = 0; r < 16; r++) acc[r] += moe_sh[r][o] * w;
        }
        float bb = tb1[t * TH + tid];
        float w2 = tw2[t * TH + tid];

        #pragma unroll
        for (int r = 0; r < 16; r++) {
            float th = fmaxf(acc[r] + bb, 0.f);
            float v = th * w2;
            for (int off = 16; off; off >>= 1)
                v += __shfl_down_sync(0xffffffffu, v, off);
            if (lane == 0) sred[r][wid] = v;
        }
        __syncthreads();
        if (tid < 16) {
            float s = 0.f;
            #pragma unroll
            for (int w = 0; w < 8; w++) s += sred[tid][w];
            out[(b0 + tid) * T + t] = s + tb2[t];
        }
        __syncthreads();
    }
}

// ---------------- launch ----------------
extern "C" void kernel_launch(void* const* d_in, const int* in_sizes, int n_in,
                              void* d_out, int out_size)
{
    const float* x     = (const float*)d_in[0];
    const float* plew  = (const float*)d_in[1];
    const float* pleb  = (const float*)d_in[2];
    const float* embW  = (const float*)d_in[3];
    const float* embb  = (const float*)d_in[4];
    const float* gW    = (const float*)d_in[5];
    const float* gb    = (const float*)d_in[6];
    const float* eW1   = (const float*)d_in[7];
    const float* eb1   = (const float*)d_in[8];
    const float* eW2   = (const float*)d_in[9];
    const float* eb2   = (const float*)d_in[10];
    const float* tw1   = (const float*)d_in[11];
    const float* tb1   = (const float*)d_in[12];
    const float* tw2   = (const float*)d_in[13];
    const float* tb2   = (const float*)d_in[14];
    float* out = (float*)d_out;

    const int SMEM_BYTES = 2 * STAGE_BYTES;   // 196608
    static bool attr_done = false;
    if (!attr_done) {
        cudaFuncSetAttribute(k_mma_gemm<F, H, 0>, cudaFuncAttributeMaxDynamicSharedMemorySize, SMEM_BYTES);
        cudaFuncSetAttribute(k_mma_gemm<H, O, 1>, cudaFuncAttributeMaxDynamicSharedMemorySize, SMEM_BYTES);
        attr_done = true;
    }

    __nv_bfloat16 *w1t_hi, *w1t_lo, *w2t_hi, *w2t_lo, *flat_hi, *flat_lo, *h_hi, *h_lo;
    cudaGetSymbolAddress((void**)&w1t_hi, g_w1t_hi);
    cudaGetSymbolAddress((void**)&w1t_lo, g_w1t_lo);
    cudaGetSymbolAddress((void**)&w2t_hi, g_w2t_hi);
    cudaGetSymbolAddress((void**)&w2t_lo, g_w2t_lo);
    cudaGetSymbolAddress((void**)&flat_hi, g_flat_hi);
    cudaGetSymbolAddress((void**)&flat_lo, g_flat_lo);
    cudaGetSymbolAddress((void**)&h_hi, g_h_hi);
    cudaGetSymbolAddress((void**)&h_lo, g_h_lo);

    k_init<<<1, 32>>>();
    k_wsplit<<<dim3(H / 32, F / 32, E), dim3(32, 8)>>>(eW1, w1t_hi, w1t_lo, F, H);
    k_wsplit<<<dim3(O / 32, H / 32, E), dim3(32, 8)>>>(eW2, w2t_hi, w2t_lo, H, O);
    k_ple<<<dim3(NF, B / 64), 256>>>(x, plew, pleb, embW, embb);
    k_gate<<<B, 256>>>(gW, gb);
    k_scan<<<1, 32>>>();
    k_assign<<<(B + 255) / 256, 256>>>();

    k_mma_gemm<F, H, 0><<<dim3(H / 128, B / GBM, E), 256, SMEM_BYTES>>>(
        flat_hi, flat_lo, w1t_hi, w1t_lo, eb1);
    k_mma_gemm<H, O, 1><<<dim3(O / 128, B / GBM, E), 256, SMEM_BYTES>>>(
        h_hi, h_lo, w2t_hi, w2t_lo, eb2);

    k_tower<<<B / 16, 256>>>(tw1, tb1, tw2, tb2, out);
}

// round 6
// speedup vs baseline: 1.3685x; 1.3685x over previous
#include <cuda_runtime.h>
#include <cuda_bf16.h>
#include <cstdint>
#include <math.h>

// Problem constants
#define B    4096
#define NF   64
#define KB   48
#define DE   64
#define F    4096
#define E    8
#define H    1024
#define O    512
#define T    2
#define TH   256

// ---------------- low-level helpers (plain sm_80+ PTX only) ----------------
__device__ __forceinline__ uint32_t smem_to_u32(const void* p) {
    uint32_t a;
    asm("{ .reg .u64 t; cvta.to.shared.u64 t, %1; cvt.u32.u64 %0, t; }" : "=r"(a) : "l"(p));
    return a;
}
__device__ __forceinline__ void cp_async16(uint32_t dst, const void* src, int src_bytes) {
    asm volatile("cp.async.cg.shared.global [%0], [%1], 16, %2;"
                 :: "r"(dst), "l"(src), "r"(src_bytes) : "memory");
}
#define CP_COMMIT() asm volatile("cp.async.commit_group;" ::: "memory")
#define CP_WAIT(n)  asm volatile("cp.async.wait_group %0;" :: "n"(n) : "memory")

__device__ __forceinline__ void ldsm_x4(uint32_t* r, uint32_t addr) {
    asm volatile("ldmatrix.sync.aligned.m8n8.x4.shared.b16 {%0,%1,%2,%3}, [%4];"
                 : "=r"(r[0]), "=r"(r[1]), "=r"(r[2]), "=r"(r[3]) : "r"(addr));
}
__device__ __forceinline__ void mma_bf16(float* c, const uint32_t* a, const uint32_t* b) {
    asm volatile(
        "mma.sync.aligned.m16n8k16.row.col.f32.bf16.bf16.f32 "
        "{%0,%1,%2,%3}, {%4,%5,%6,%7}, {%8,%9}, {%0,%1,%2,%3};"
        : "+f"(c[0]), "+f"(c[1]), "+f"(c[2]), "+f"(c[3])
        : "r"(a[0]), "r"(a[1]), "r"(a[2]), "r"(a[3]), "r"(b[0]), "r"(b[1]));
}

// ---------------- device scratch ----------------
__device__ __nv_bfloat16 g_flat_hi[(size_t)B * F];     // 32 MB
__device__ __nv_bfloat16 g_flat_lo[(size_t)B * F];     // 32 MB
__device__ __nv_bfloat16 g_w1t_hi[(size_t)E * H * F];  // 64 MB  [e][h][f]
__device__ __nv_bfloat16 g_w1t_lo[(size_t)E * H * F];  // 64 MB
__device__ __nv_bfloat16 g_w2t_hi[(size_t)E * O * H];  // 8 MB   [e][o][h]
__device__ __nv_bfloat16 g_w2t_lo[(size_t)E * O * H];  // 8 MB
__device__ __nv_bfloat16 g_h_hi[(size_t)2 * B * H];    // 16 MB
__device__ __nv_bfloat16 g_h_lo[(size_t)2 * B * H];    // 16 MB
__device__ float g_eo[(size_t)2 * B * O];              // 16 MB
__device__ int   g_count[E];
__device__ int   g_base[E];
__device__ int   g_cursor[E];
__device__ int   g_te[B * 2];
__device__ float g_tg[B * 2];
__device__ int   g_rows[2 * B];
__device__ float g_gates[2 * B];
__device__ int   g_pair[B * 2];

// ---------------- init ----------------
__global__ void k_init() {
    if (threadIdx.x < E) g_count[threadIdx.x] = 0;
}

// ---------------- weight split + transpose: W[e][k][n] -> T[e][n][k] bf16 hi/lo ----------------
__global__ __launch_bounds__(256) void k_wsplit(
    const float* __restrict__ W, __nv_bfloat16* __restrict__ Thi,
    __nv_bfloat16* __restrict__ Tlo, int Kdim, int Ndim)
{
    __shared__ float t[32][33];
    int e = blockIdx.z;
    int kb = blockIdx.y * 32;
    int nb = blockIdx.x * 32;
    int tx = threadIdx.x, ty = threadIdx.y;
    const float* Wb = W + (size_t)e * Kdim * Ndim;
    #pragma unroll
    for (int i = ty; i < 32; i += 8)
        t[i][tx] = Wb[(size_t)(kb + i) * Ndim + nb + tx];
    __syncthreads();
    #pragma unroll
    for (int i = ty; i < 32; i += 8) {
        float v = t[tx][i];
        __nv_bfloat16 h = __float2bfloat16(v);
        __nv_bfloat16 l = __float2bfloat16(v - __bfloat162float(h));
        size_t o = ((size_t)e * Ndim + nb + i) * Kdim + kb + tx;
        Thi[o] = h; Tlo[o] = l;
    }
}

// ---------------- PLE + embedding + ReLU -> flat hi/lo ----------------
// grid (NF, B/64), block 256. 64 rows per block; thread = (4 rows) x (4 d-cols).
__global__ __launch_bounds__(256) void k_ple(
    const float* __restrict__ x, const float* __restrict__ plew,
    const float* __restrict__ pleb, const float* __restrict__ embW,
    const float* __restrict__ embb)
{
    int n = blockIdx.x;
    int b0 = blockIdx.y * 64;
    int tid = threadIdx.x;

    __shared__ float Wsh[KB * DE];      // 12 KB
    __shared__ float wsh[KB], bsh[KB], ebias[DE];
    __shared__ float xs[64];
    __shared__ float enc_sh[64][KB];    // 12 KB

    for (int i = tid; i < KB * DE; i += 256) Wsh[i] = embW[(size_t)n * KB * DE + i];
    if (tid < KB) { wsh[tid] = plew[n * KB + tid]; bsh[tid] = pleb[n * KB + tid]; }
    if (tid < DE) ebias[tid] = embb[n * DE + tid];
    if (tid < 64) xs[tid] = x[(b0 + tid) * NF + n];
    __syncthreads();

    for (int idx = tid; idx < 64 * KB; idx += 256) {
        int bl = idx / KB, k = idx - bl * KB;
        float enc = bsh[k] + wsh[k] * xs[bl];
        if (k == 0)           enc = fminf(enc, 1.f);
        else if (k == KB - 1) enc = fmaxf(enc, 0.f);
        else                  enc = fminf(fmaxf(enc, 0.f), 1.f);
        enc_sh[bl][k] = enc;
    }
    __syncthreads();

    int c0 = (tid & 15) * 4;
    int r0 = (tid >> 4) * 4;

    float acc[4][4];
    #pragma unroll
    for (int r = 0; r < 4; r++)
        #pragma unroll
        for (int j = 0; j < 4; j++) acc[r][j] = ebias[c0 + j];

    #pragma unroll
    for (int k4 = 0; k4 < KB; k4 += 4) {
        float4 wv[4];
        #pragma unroll
        for (int kk = 0; kk < 4; kk++)
            wv[kk] = *(const float4*)&Wsh[(k4 + kk) * DE + c0];
        #pragma unroll
        for (int r = 0; r < 4; r++) {
            float4 ev = *(const float4*)&enc_sh[r0 + r][k4];
            const float* w0 = (const float*)&wv[0];
            const float* w1 = (const float*)&wv[1];
            const float* w2 = (const float*)&wv[2];
            const float* w3 = (const float*)&wv[3];
            #pragma unroll
            for (int j = 0; j < 4; j++)
                acc[r][j] += ev.x * w0[j] + ev.y * w1[j] + ev.z * w2[j] + ev.w * w3[j];
        }
    }

    #pragma unroll
    for (int r = 0; r < 4; r++) {
        int b = b0 + r0 + r;
        uint32_t hw[2], lw[2];
        #pragma unroll
        for (int p = 0; p < 2; p++) {
            float v0 = fmaxf(acc[r][p * 2 + 0], 0.f);
            float v1 = fmaxf(acc[r][p * 2 + 1], 0.f);
            __nv_bfloat16 h0 = __float2bfloat16(v0);
            __nv_bfloat16 h1 = __float2bfloat16(v1);
            __nv_bfloat16 l0 = __float2bfloat16(v0 - __bfloat162float(h0));
            __nv_bfloat16 l1 = __float2bfloat16(v1 - __bfloat162float(h1));
            __nv_bfloat162 hh = __halves2bfloat162(h0, h1);
            __nv_bfloat162 ll = __halves2bfloat162(l0, l1);
            hw[p] = *(uint32_t*)&hh;
            lw[p] = *(uint32_t*)&ll;
        }
        size_t idx = (size_t)b * F + n * DE + c0;
        *(uint2*)&g_flat_hi[idx] = make_uint2(hw[0], hw[1]);
        *(uint2*)&g_flat_lo[idx] = make_uint2(lw[0], lw[1]);
    }
}

// ---------------- gate ----------------
__global__ __launch_bounds__(256) void k_gate(
    const float* __restrict__ gW, const float* __restrict__ gb)
{
    int b = blockIdx.x;
    int tid = threadIdx.x;
    int lane = tid & 31, wid = tid >> 5;

    float acc[E];
    #pragma unroll
    for (int e = 0; e < E; e++) acc[e] = 0.f;

    const __nv_bfloat16* xh = g_flat_hi + (size_t)b * F;
    const __nv_bfloat16* xl = g_flat_lo + (size_t)b * F;
    for (int f = tid; f < F; f += 256) {
        float xv = __bfloat162float(xh[f]) + __bfloat162float(xl[f]);
        #pragma unroll
        for (int e = 0; e < E; e++) acc[e] += xv * gW[f * E + e];
    }
    #pragma unroll
    for (int e = 0; e < E; e++)
        for (int off = 16; off; off >>= 1)
            acc[e] += __shfl_down_sync(0xffffffffu, acc[e], off);

    __shared__ float sb[E][8];
    __shared__ float slog[E];
    if (lane == 0) {
        #pragma unroll
        for (int e = 0; e < E; e++) sb[e][wid] = acc[e];
    }
    __syncthreads();
    if (tid < E) {
        float s = 0.f;
        #pragma unroll
        for (int w = 0; w < 8; w++) s += sb[tid][w];
        slog[tid] = s + gb[tid];
    }
    __syncthreads();
    if (tid == 0) {
        int i0 = 0;
        #pragma unroll
        for (int e = 1; e < E; e++) if (slog[e] > slog[i0]) i0 = e;
        int i1 = (i0 == 0) ? 1 : 0;
        #pragma unroll
        for (int e = 0; e < E; e++) if (e != i0 && slog[e] > slog[i1]) i1 = e;
        float e1 = __expf(slog[i1] - slog[i0]);
        float inv = 1.f / (1.f + e1);
        g_te[b * 2 + 0] = i0;  g_tg[b * 2 + 0] = inv;
        g_te[b * 2 + 1] = i1;  g_tg[b * 2 + 1] = e1 * inv;
        atomicAdd(&g_count[i0], 1);
        atomicAdd(&g_count[i1], 1);
    }
}

__global__ void k_scan() {
    if (threadIdx.x == 0) {
        int s = 0;
        for (int e = 0; e < E; e++) { g_base[e] = s; g_cursor[e] = s; s += g_count[e]; }
    }
}

__global__ __launch_bounds__(256) void k_assign() {
    int b = blockIdx.x * 256 + threadIdx.x;
    if (b >= B) return;
    #pragma unroll
    for (int j = 0; j < 2; j++) {
        int e = g_te[b * 2 + j];
        int slot = atomicAdd(&g_cursor[e], 1);
        g_rows[slot]  = b;
        g_gates[slot] = g_tg[b * 2 + j];
        g_pair[b * 2 + j] = slot;
    }
}

// ---------------- split-bf16 register-MMA expert GEMM ----------------
// CTA tile 128x128, 8 warps (2m x 4n), warp tile 64x32, k-tile 32.
// SMEM row layout per tile row: [hi 64B | lo 64B] (128B, SW128 swizzle).
// 3-stage cp.async pipeline, 32KB/stage, 96KB total -> 2 CTAs/SM.
#define GBM 128
#define GKT 32
#define STAGE_BYTES 32768
#define OFF_A 0
#define OFF_B 16384

template<int KTOT, int NTOT, int MODE>
__global__ __launch_bounds__(256, 2) void k_mma_gemm(
    const __nv_bfloat16* __restrict__ Ahi, const __nv_bfloat16* __restrict__ Alo,
    const __nv_bfloat16* __restrict__ Whi, const __nv_bfloat16* __restrict__ Wlo,
    const float* __restrict__ bias)
{
    int e = blockIdx.z;
    int cnt = g_count[e];
    int m0 = blockIdx.y * GBM;
    if (m0 >= cnt) return;
    int base = g_base[e];
    int n0 = blockIdx.x * 128;

    extern __shared__ char smem[];
    uint32_t sb = smem_to_u32(smem);
    __shared__ int rows_s[GBM];

    int tid = threadIdx.x;
    int lane = tid & 31, wid = tid >> 5;

    if (MODE == 0 && tid < GBM) {
        int m = m0 + tid;
        rows_s[tid] = (m < cnt) ? g_rows[base + m] : -1;
    }
    __syncthreads();

    // -------- loader setup: thread -> (row 0..127, 4 of 8 16B chunks) --------
    // chunk ch<4: hi plane bytes [ch*16, ch*16+16); ch>=4: lo plane at +64B.
    int lrow = tid >> 1;
    int lcb  = (tid & 1) * 4;     // 0 -> chunks 0..3 (hi), 4 -> chunks 4..7 (lo)
    uint32_t lsw = (uint32_t)((lrow & 7) << 4);
    uint32_t lbase = (uint32_t)(lrow * 128);

    const __nv_bfloat16 *arow;
    int abytes;
    if (MODE == 0) {
        int gr = rows_s[lrow];
        abytes = (gr >= 0) ? 16 : 0;
        int r = (gr >= 0) ? gr : 0;
        arow = ((lcb == 0) ? Ahi : Alo) + (size_t)r * KTOT;
    } else {
        int m = m0 + lrow;
        abytes = (m < cnt) ? 16 : 0;
        size_t r = (m < cnt) ? (size_t)(base + m) : 0;
        arow = ((lcb == 0) ? Ahi : Alo) + r * KTOT;
    }
    const __nv_bfloat16* brow = ((lcb == 0) ? Whi : Wlo) + ((size_t)e * NTOT + n0 + lrow) * KTOT;

    // -------- mma setup: 8 warps = 2m x 4n, warp tile 64x32 --------
    int wm = wid >> 2;            // 0..1
    int wn = wid & 3;             // 0..3
    int a_row = wm * 64 + (lane & 15);
    uint32_t a_c  = (uint32_t)((lane >> 4) * 16);
    uint32_t asw  = (uint32_t)((a_row & 7) << 4);
    int b_row = wn * 32 + (lane & 7) + ((lane >> 4) << 3);
    uint32_t b_c  = (uint32_t)(((lane >> 3) & 1) * 16);
    uint32_t bsw  = (uint32_t)((b_row & 7) << 4);

    float acc[4][4][4];
    #pragma unroll
    for (int i = 0; i < 4; i++)
        #pragma unroll
        for (int j = 0; j < 4; j++)
            #pragma unroll
            for (int q = 0; q < 4; q++) acc[i][j][q] = 0.f;

    const int NT = KTOT / GKT;

    // loader lambda-ish macro: fill stage buffer for k-tile kt
    #define LOAD_STAGE(stg, kt_) do {                                            \
        uint32_t s_ = sb + (uint32_t)(stg) * STAGE_BYTES;                         \
        int k0_ = (kt_) * GKT;                                                    \
        _Pragma("unroll")                                                         \
        for (int q = 0; q < 4; q++) {                                             \
            int ch = lcb + q;                                                     \
            uint32_t so = lbase + (((uint32_t)(ch * 16)) ^ lsw);                  \
            cp_async16(s_ + OFF_A + so, arow + k0_ + q * 8, abytes);              \
            cp_async16(s_ + OFF_B + so, brow + k0_ + q * 8, 16);                  \
        }                                                                         \
        CP_COMMIT();                                                              \
    } while (0)

    // prime stages 0..2
    LOAD_STAGE(0, 0);
    if (NT > 1) LOAD_STAGE(1, 1);
    if (NT > 2) LOAD_STAGE(2, 2);

    int stg = 0;
    for (int kt = 0; kt < NT; kt++) {
        if (kt + 3 < NT) CP_WAIT(2);
        else if (kt + 2 < NT) CP_WAIT(2);
        else if (kt + 1 < NT) CP_WAIT(1);
        else CP_WAIT(0);
        __syncthreads();

        uint32_t s0 = sb + (uint32_t)stg * STAGE_BYTES;
        #pragma unroll
        for (int kk = 0; kk < 2; kk++) {
            uint32_t ah[4][4], al[4][4], bh[2][4], bl[2][4];
            #pragma unroll
            for (int i = 0; i < 4; i++) {
                uint32_t ro = (uint32_t)((a_row + i * 16) * 128);
                uint32_t chi = (a_c + kk * 32) ^ asw;
                uint32_t clo = (64 + a_c + kk * 32) ^ asw;
                ldsm_x4(ah[i], s0 + OFF_A + ro + chi);
                ldsm_x4(al[i], s0 + OFF_A + ro + clo);
            }
            #pragma unroll
            for (int p = 0; p < 2; p++) {
                uint32_t ro = (uint32_t)((b_row + p * 16) * 128);
                uint32_t chi = (b_c + kk * 32) ^ bsw;
                uint32_t clo = (64 + b_c + kk * 32) ^ bsw;
                ldsm_x4(bh[p], s0 + OFF_B + ro + chi);
                ldsm_x4(bl[p], s0 + OFF_B + ro + clo);
            }
            #pragma unroll
            for (int i = 0; i < 4; i++)
                #pragma unroll
                for (int j = 0; j < 4; j++) {
                    const uint32_t* bhj = &bh[j >> 1][(j & 1) * 2];
                    const uint32_t* blj = &bl[j >> 1][(j & 1) * 2];
                    mma_bf16(acc[i][j], ah[i], bhj);
                    mma_bf16(acc[i][j], ah[i], blj);
                    mma_bf16(acc[i][j], al[i], bhj);
                }
        }
        __syncthreads();
        if (kt + 3 < NT) LOAD_STAGE(stg, kt + 3);
        stg = (stg == 2) ? 0 : stg + 1;
    }
    #undef LOAD_STAGE

    // -------- epilogue --------
    int g = lane >> 2;
    int cg = (lane & 3) * 2;
    #pragma unroll
    for (int i = 0; i < 4; i++) {
        #pragma unroll
        for (int half = 0; half < 2; half++) {
            int m = m0 + wm * 64 + i * 16 + g + half * 8;
            if (m < cnt) {
                int slot = base + m;
                float gate = (MODE == 1) ? g_gates[slot] : 0.f;
                #pragma unroll
                for (int j = 0; j < 4; j++) {
                    int col = n0 + wn * 32 + j * 8 + cg;
                    float bv0 = bias[(size_t)e * NTOT + col];
                    float bv1 = bias[(size_t)e * NTOT + col + 1];
                    float v0 = acc[i][j][half * 2 + 0] + bv0;
                    float v1 = acc[i][j][half * 2 + 1] + bv1;
                    if (MODE == 0) {
                        v0 = fmaxf(v0, 0.f); v1 = fmaxf(v1, 0.f);
                        __nv_bfloat16 h0 = __float2bfloat16(v0);
                        __nv_bfloat16 h1 = __float2bfloat16(v1);
                        __nv_bfloat16 l0 = __float2bfloat16(v0 - __bfloat162float(h0));
                        __nv_bfloat16 l1 = __float2bfloat16(v1 - __bfloat162float(h1));
                        __nv_bfloat162 hh = __halves2bfloat162(h0, h1);
                        __nv_bfloat162 ll = __halves2bfloat162(l0, l1);
                        *(uint32_t*)&g_h_hi[(size_t)slot * H + col] = *(uint32_t*)&hh;
                        *(uint32_t*)&g_h_lo[(size_t)slot * H + col] = *(uint32_t*)&ll;
                    } else {
                        float2 v = make_float2(gate * v0, gate * v1);
                        *(float2*)&g_eo[(size_t)slot * O + col] = v;
                    }
                }
            }
        }
    }
}

// ---------------- task towers ----------------
__global__ __launch_bounds__(256) void k_tower(
    const float* __restrict__ tw1, const float* __restrict__ tb1,
    const float* __restrict__ tw2, const float* __restrict__ tb2,
    float* __restrict__ out)
{
    int b0 = blockIdx.x * 16;
    int tid = threadIdx.x;
    int lane = tid & 31, wid = tid >> 5;

    __shared__ float moe_sh[16][O];
    __shared__ float sred[16][8];

    #pragma unroll
    for (int r = 0; r < 16; r++) {
        int b = b0 + r;
        int s0 = g_pair[b * 2 + 0], s1 = g_pair[b * 2 + 1];
        for (int c = tid; c < O; c += 256)
            moe_sh[r][c] = g_eo[(size_t)s0 * O + c] + g_eo[(size_t)s1 * O + c];
    }
    __syncthreads();

    for (int t = 0; t < T; t++) {
        float acc[16];
        #pragma unroll
        for (int r = 0; r < 16; r++) acc[r] = 0.f;

        const float* w1 = tw1 + (size_t)t * O * TH + tid;
        for (int o = 0; o < O; o++) {
            float w = w1[(size_t)o * TH];
            #pragma unroll
            for (int r = 0; r < 16; r++) acc[r] += moe_sh[r][o] * w;
        }
        float bb = tb1[t * TH + tid];
        float w2 = tw2[t * TH + tid];

        #pragma unroll
        for (int r = 0; r < 16; r++) {
            float th = fmaxf(acc[r] + bb, 0.f);
            float v = th * w2;
            for (int off = 16; off; off >>= 1)
                v += __shfl_down_sync(0xffffffffu, v, off);
            if (lane == 0) sred[r][wid] = v;
        }
        __syncthreads();
        if (tid < 16) {
            float s = 0.f;
            #pragma unroll
            for (int w = 0; w < 8; w++) s += sred[tid][w];
            out[(b0 + tid) * T + t] = s + tb2[t];
        }
        __syncthreads();
    }
}

// ---------------- launch ----------------
extern "C" void kernel_launch(void* const* d_in, const int* in_sizes, int n_in,
                              void* d_out, int out_size)
{
    const float* x     = (const float*)d_in[0];
    const float* plew  = (const float*)d_in[1];
    const float* pleb  = (const float*)d_in[2];
    const float* embW  = (const float*)d_in[3];
    const float* embb  = (const float*)d_in[4];
    const float* gW    = (const float*)d_in[5];
    const float* gb    = (const float*)d_in[6];
    const float* eW1   = (const float*)d_in[7];
    const float* eb1   = (const float*)d_in[8];
    const float* eW2   = (const float*)d_in[9];
    const float* eb2   = (const float*)d_in[10];
    const float* tw1   = (const float*)d_in[11];
    const float* tb1   = (const float*)d_in[12];
    const float* tw2   = (const float*)d_in[13];
    const float* tb2   = (const float*)d_in[14];
    float* out = (float*)d_out;

    const int SMEM_BYTES = 3 * STAGE_BYTES;   // 98304
    static bool attr_done = false;
    if (!attr_done) {
        cudaFuncSetAttribute(k_mma_gemm<F, H, 0>, cudaFuncAttributeMaxDynamicSharedMemorySize, SMEM_BYTES);
        cudaFuncSetAttribute(k_mma_gemm<H, O, 1>, cudaFuncAttributeMaxDynamicSharedMemorySize, SMEM_BYTES);
        attr_done = true;
    }

    __nv_bfloat16 *w1t_hi, *w1t_lo, *w2t_hi, *w2t_lo, *flat_hi, *flat_lo, *h_hi, *h_lo;
    cudaGetSymbolAddress((void**)&w1t_hi, g_w1t_hi);
    cudaGetSymbolAddress((void**)&w1t_lo, g_w1t_lo);
    cudaGetSymbolAddress((void**)&w2t_hi, g_w2t_hi);
    cudaGetSymbolAddress((void**)&w2t_lo, g_w2t_lo);
    cudaGetSymbolAddress((void**)&flat_hi, g_flat_hi);
    cudaGetSymbolAddress((void**)&flat_lo, g_flat_lo);
    cudaGetSymbolAddress((void**)&h_hi, g_h_hi);
    cudaGetSymbolAddress((void**)&h_lo, g_h_lo);

    k_init<<<1, 32>>>();
    k_wsplit<<<dim3(H / 32, F / 32, E), dim3(32, 8)>>>(eW1, w1t_hi, w1t_lo, F, H);
    k_wsplit<<<dim3(O / 32, H / 32, E), dim3(32, 8)>>>(eW2, w2t_hi, w2t_lo, H, O);
    k_ple<<<dim3(NF, B / 64), 256>>>(x, plew, pleb, embW, embb);
    k_gate<<<B, 256>>>(gW, gb);
    k_scan<<<1, 32>>>();
    k_assign<<<(B + 255) / 256, 256>>>();

    k_mma_gemm<F, H, 0><<<dim3(H / 128, B / GBM, E), 256, SMEM_BYTES>>>(
        flat_hi, flat_lo, w1t_hi, w1t_lo, eb1);
    k_mma_gemm<H, O, 1><<<dim3(O / 128, B / GBM, E), 256, SMEM_BYTES>>>(
        h_hi, h_lo, w2t_hi, w2t_lo, eb2);

    k_tower<<<B / 16, 256>>>(tw1, tb1, tw2, tb2, out);
}

// round 7
// speedup vs baseline: 1.5829x; 1.1567x over previous
#include <cuda_runtime.h>
#include <cuda_bf16.h>
#include <cstdint>
#include <math.h>

// Problem constants
#define B    4096
#define NF   64
#define KB   48
#define DE   64
#define F    4096
#define E    8
#define H    1024
#define O    512
#define T    2
#define TH   256

// ---------------- low-level helpers (plain sm_80+ PTX only) ----------------
__device__ __forceinline__ uint32_t smem_to_u32(const void* p) {
    uint32_t a;
    asm("{ .reg .u64 t; cvta.to.shared.u64 t, %1; cvt.u32.u64 %0, t; }" : "=r"(a) : "l"(p));
    return a;
}
__device__ __forceinline__ void cp_async16(uint32_t dst, const void* src, int src_bytes) {
    asm volatile("cp.async.cg.shared.global [%0], [%1], 16, %2;"
                 :: "r"(dst), "l"(src), "r"(src_bytes) : "memory");
}
#define CP_COMMIT() asm volatile("cp.async.commit_group;" ::: "memory")
#define CP_WAIT(n)  asm volatile("cp.async.wait_group %0;" :: "n"(n) : "memory")

__device__ __forceinline__ void ldsm_x4(uint32_t* r, uint32_t addr) {
    asm volatile("ldmatrix.sync.aligned.m8n8.x4.shared.b16 {%0,%1,%2,%3}, [%4];"
                 : "=r"(r[0]), "=r"(r[1]), "=r"(r[2]), "=r"(r[3]) : "r"(addr));
}
__device__ __forceinline__ void mma_bf16(float* c, const uint32_t* a, const uint32_t* b) {
    asm volatile(
        "mma.sync.aligned.m16n8k16.row.col.f32.bf16.bf16.f32 "
        "{%0,%1,%2,%3}, {%4,%5,%6,%7}, {%8,%9}, {%0,%1,%2,%3};"
        : "+f"(c[0]), "+f"(c[1]), "+f"(c[2]), "+f"(c[3])
        : "r"(a[0]), "r"(a[1]), "r"(a[2]), "r"(a[3]), "r"(b[0]), "r"(b[1]));
}

// ---------------- device scratch ----------------
__device__ __nv_bfloat16 g_flat_hi[(size_t)B * F];     // 32 MB
__device__ __nv_bfloat16 g_flat_lo[(size_t)B * F];     // 32 MB
__device__ __nv_bfloat16 g_w1t_hi[(size_t)E * H * F];  // 64 MB  [e][h][f]
__device__ __nv_bfloat16 g_w1t_lo[(size_t)E * H * F];  // 64 MB
__device__ __nv_bfloat16 g_w2t_hi[(size_t)E * O * H];  // 8 MB   [e][o][h]
__device__ __nv_bfloat16 g_w2t_lo[(size_t)E * O * H];  // 8 MB
__device__ __nv_bfloat16 g_h_hi[(size_t)2 * B * H];    // 16 MB
__device__ __nv_bfloat16 g_h_lo[(size_t)2 * B * H];    // 16 MB
__device__ float g_eo[(size_t)2 * B * O];              // 16 MB
__device__ int   g_count[E];
__device__ int   g_base[E];
__device__ int   g_cursor[E];
__device__ int   g_te[B * 2];
__device__ float g_tg[B * 2];
__device__ int   g_rows[2 * B];
__device__ float g_gates[2 * B];
__device__ int   g_pair[B * 2];

// ---------------- init ----------------
__global__ void k_init() {
    if (threadIdx.x < E) g_count[threadIdx.x] = 0;
}

// ---------------- weight split + transpose: W[e][k][n] -> T[e][n][k] bf16 hi/lo ----------------
__global__ __launch_bounds__(256) void k_wsplit(
    const float* __restrict__ W, __nv_bfloat16* __restrict__ Thi,
    __nv_bfloat16* __restrict__ Tlo, int Kdim, int Ndim)
{
    __shared__ float t[32][33];
    int e = blockIdx.z;
    int kb = blockIdx.y * 32;
    int nb = blockIdx.x * 32;
    int tx = threadIdx.x, ty = threadIdx.y;
    const float* Wb = W + (size_t)e * Kdim * Ndim;
    #pragma unroll
    for (int i = ty; i < 32; i += 8)
        t[i][tx] = Wb[(size_t)(kb + i) * Ndim + nb + tx];
    __syncthreads();
    #pragma unroll
    for (int i = ty; i < 32; i += 8) {
        float v = t[tx][i];
        __nv_bfloat16 h = __float2bfloat16(v);
        __nv_bfloat16 l = __float2bfloat16(v - __bfloat162float(h));
        size_t o = ((size_t)e * Ndim + nb + i) * Kdim + kb + tx;
        Thi[o] = h; Tlo[o] = l;
    }
}

// ---------------- PLE + embedding + ReLU -> flat hi/lo ----------------
// grid (NF, B/64), block 256. 64 rows per block; thread = (4 rows) x (4 d-cols).
__global__ __launch_bounds__(256) void k_ple(
    const float* __restrict__ x, const float* __restrict__ plew,
    const float* __restrict__ pleb, const float* __restrict__ embW,
    const float* __restrict__ embb)
{
    int n = blockIdx.x;
    int b0 = blockIdx.y * 64;
    int tid = threadIdx.x;

    __shared__ float Wsh[KB * DE];      // 12 KB
    __shared__ float wsh[KB], bsh[KB], ebias[DE];
    __shared__ float xs[64];
    __shared__ float enc_sh[64][KB];    // 12 KB

    for (int i = tid; i < KB * DE; i += 256) Wsh[i] = embW[(size_t)n * KB * DE + i];
    if (tid < KB) { wsh[tid] = plew[n * KB + tid]; bsh[tid] = pleb[n * KB + tid]; }
    if (tid < DE) ebias[tid] = embb[n * DE + tid];
    if (tid < 64) xs[tid] = x[(b0 + tid) * NF + n];
    __syncthreads();

    for (int idx = tid; idx < 64 * KB; idx += 256) {
        int bl = idx / KB, k = idx - bl * KB;
        float enc = bsh[k] + wsh[k] * xs[bl];
        if (k == 0)           enc = fminf(enc, 1.f);
        else if (k == KB - 1) enc = fmaxf(enc, 0.f);
        else                  enc = fminf(fmaxf(enc, 0.f), 1.f);
        enc_sh[bl][k] = enc;
    }
    __syncthreads();

    int c0 = (tid & 15) * 4;
    int r0 = (tid >> 4) * 4;

    float acc[4][4];
    #pragma unroll
    for (int r = 0; r < 4; r++)
        #pragma unroll
        for (int j = 0; j < 4; j++) acc[r][j] = ebias[c0 + j];

    #pragma unroll
    for (int k4 = 0; k4 < KB; k4 += 4) {
        float4 wv[4];
        #pragma unroll
        for (int kk = 0; kk < 4; kk++)
            wv[kk] = *(const float4*)&Wsh[(k4 + kk) * DE + c0];
        #pragma unroll
        for (int r = 0; r < 4; r++) {
            float4 ev = *(const float4*)&enc_sh[r0 + r][k4];
            const float* w0 = (const float*)&wv[0];
            const float* w1 = (const float*)&wv[1];
            const float* w2 = (const float*)&wv[2];
            const float* w3 = (const float*)&wv[3];
            #pragma unroll
            for (int j = 0; j < 4; j++)
                acc[r][j] += ev.x * w0[j] + ev.y * w1[j] + ev.z * w2[j] + ev.w * w3[j];
        }
    }

    #pragma unroll
    for (int r = 0; r < 4; r++) {
        int b = b0 + r0 + r;
        uint32_t hw[2], lw[2];
        #pragma unroll
        for (int p = 0; p < 2; p++) {
            float v0 = fmaxf(acc[r][p * 2 + 0], 0.f);
            float v1 = fmaxf(acc[r][p * 2 + 1], 0.f);
            __nv_bfloat16 h0 = __float2bfloat16(v0);
            __nv_bfloat16 h1 = __float2bfloat16(v1);
            __nv_bfloat16 l0 = __float2bfloat16(v0 - __bfloat162float(h0));
            __nv_bfloat16 l1 = __float2bfloat16(v1 - __bfloat162float(h1));
            __nv_bfloat162 hh = __halves2bfloat162(h0, h1);
            __nv_bfloat162 ll = __halves2bfloat162(l0, l1);
            hw[p] = *(uint32_t*)&hh;
            lw[p] = *(uint32_t*)&ll;
        }
        size_t idx = (size_t)b * F + n * DE + c0;
        *(uint2*)&g_flat_hi[idx] = make_uint2(hw[0], hw[1]);
        *(uint2*)&g_flat_lo[idx] = make_uint2(lw[0], lw[1]);
    }
}

// ---------------- gate ----------------
__global__ __launch_bounds__(256) void k_gate(
    const float* __restrict__ gW, const float* __restrict__ gb)
{
    int b = blockIdx.x;
    int tid = threadIdx.x;
    int lane = tid & 31, wid = tid >> 5;

    float acc[E];
    #pragma unroll
    for (int e = 0; e < E; e++) acc[e] = 0.f;

    const __nv_bfloat16* xh = g_flat_hi + (size_t)b * F;
    const __nv_bfloat16* xl = g_flat_lo + (size_t)b * F;
    for (int f = tid; f < F; f += 256) {
        float xv = __bfloat162float(xh[f]) + __bfloat162float(xl[f]);
        #pragma unroll
        for (int e = 0; e < E; e++) acc[e] += xv * gW[f * E + e];
    }
    #pragma unroll
    for (int e = 0; e < E; e++)
        for (int off = 16; off; off >>= 1)
            acc[e] += __shfl_down_sync(0xffffffffu, acc[e], off);

    __shared__ float sb[E][8];
    __shared__ float slog[E];
    if (lane == 0) {
        #pragma unroll
        for (int e = 0; e < E; e++) sb[e][wid] = acc[e];
    }
    __syncthreads();
    if (tid < E) {
        float s = 0.f;
        #pragma unroll
        for (int w = 0; w < 8; w++) s += sb[tid][w];
        slog[tid] = s + gb[tid];
    }
    __syncthreads();
    if (tid == 0) {
        int i0 = 0;
        #pragma unroll
        for (int e = 1; e < E; e++) if (slog[e] > slog[i0]) i0 = e;
        int i1 = (i0 == 0) ? 1 : 0;
        #pragma unroll
        for (int e = 0; e < E; e++) if (e != i0 && slog[e] > slog[i1]) i1 = e;
        float e1 = __expf(slog[i1] - slog[i0]);
        float inv = 1.f / (1.f + e1);
        g_te[b * 2 + 0] = i0;  g_tg[b * 2 + 0] = inv;
        g_te[b * 2 + 1] = i1;  g_tg[b * 2 + 1] = e1 * inv;
        atomicAdd(&g_count[i0], 1);
        atomicAdd(&g_count[i1], 1);
    }
}

__global__ void k_scan() {
    if (threadIdx.x == 0) {
        int s = 0;
        for (int e = 0; e < E; e++) { g_base[e] = s; g_cursor[e] = s; s += g_count[e]; }
    }
}

__global__ __launch_bounds__(256) void k_assign() {
    int b = blockIdx.x * 256 + threadIdx.x;
    if (b >= B) return;
    #pragma unroll
    for (int j = 0; j < 2; j++) {
        int e = g_te[b * 2 + j];
        int slot = atomicAdd(&g_cursor[e], 1);
        g_rows[slot]  = b;
        g_gates[slot] = g_tg[b * 2 + j];
        g_pair[b * 2 + j] = slot;
    }
}

// ---------------- split-bf16 register-MMA expert GEMM ----------------
// CTA tile 128x128, 8 warps (2m x 4n), warp tile 64x32, k-tile 64, 3-stage cp.async.
#define GBM 128
#define GKT 64
#define STAGE_BYTES 65536
#define OFF_AHI 0
#define OFF_ALO 16384
#define OFF_BHI 32768
#define OFF_BLO 49152

template<int KTOT, int NTOT, int MODE>
__global__ __launch_bounds__(256, 1) void k_mma_gemm(
    const __nv_bfloat16* __restrict__ Ahi, const __nv_bfloat16* __restrict__ Alo,
    const __nv_bfloat16* __restrict__ Whi, const __nv_bfloat16* __restrict__ Wlo,
    const float* __restrict__ bias)
{
    int e = blockIdx.z;
    int cnt = g_count[e];
    int m0 = blockIdx.y * GBM;
    if (m0 >= cnt) return;
    int base = g_base[e];
    int n0 = blockIdx.x * 128;

    extern __shared__ char smem[];
    uint32_t sb = smem_to_u32(smem);
    __shared__ int rows_s[GBM];

    int tid = threadIdx.x;
    int lane = tid & 31, wid = tid >> 5;

    if (MODE == 0 && tid < GBM) {
        int m = m0 + tid;
        rows_s[tid] = (m < cnt) ? g_rows[base + m] : -1;
    }
    __syncthreads();

    // -------- loader setup: thread -> (row 0..127, 4 chunks of 16B) --------
    int lrow = tid >> 1;
    int lcb  = (tid & 1) * 4;
    const __nv_bfloat16 *arow_hi, *arow_lo;
    int abytes;
    if (MODE == 0) {
        int gr = rows_s[lrow];
        abytes = (gr >= 0) ? 16 : 0;
        int r = (gr >= 0) ? gr : 0;
        arow_hi = Ahi + (size_t)r * KTOT;
        arow_lo = Alo + (size_t)r * KTOT;
    } else {
        int m = m0 + lrow;
        abytes = (m < cnt) ? 16 : 0;
        size_t r = (m < cnt) ? (size_t)(base + m) : 0;
        arow_hi = Ahi + r * KTOT;
        arow_lo = Alo + r * KTOT;
    }
    const __nv_bfloat16* brow_hi = Whi + ((size_t)e * NTOT + n0 + lrow) * KTOT;
    const __nv_bfloat16* brow_lo = Wlo + ((size_t)e * NTOT + n0 + lrow) * KTOT;
    uint32_t lsw = (uint32_t)((lrow & 7) << 4);
    uint32_t lbase = (uint32_t)(lrow * 128);

    // -------- mma setup --------
    int wm = wid >> 2;            // 0..1
    int wn = wid & 3;             // 0..3
    int a_row = wm * 64 + (lane & 15);
    uint32_t a_c  = (uint32_t)((lane >> 4) * 16);
    uint32_t asw  = (uint32_t)((a_row & 7) << 4);
    int b_row = wn * 32 + (lane & 7) + ((lane >> 4) << 3);
    uint32_t b_c  = (uint32_t)(((lane >> 3) & 1) * 16);
    uint32_t bsw  = (uint32_t)((b_row & 7) << 4);

    float acc[4][4][4];
    #pragma unroll
    for (int i = 0; i < 4; i++)
        #pragma unroll
        for (int j = 0; j < 4; j++)
            #pragma unroll
            for (int q = 0; q < 4; q++) acc[i][j][q] = 0.f;

    const int NT = KTOT / GKT;

    #define LOAD_STAGE(stg_, kt_) do {                                           \
        uint32_t s_ = sb + (uint32_t)(stg_) * STAGE_BYTES;                        \
        int k0_ = (kt_) * GKT;                                                    \
        _Pragma("unroll")                                                         \
        for (int q = 0; q < 4; q++) {                                             \
            int ch = lcb + q;                                                     \
            uint32_t so = lbase + (((uint32_t)(ch * 16)) ^ lsw);                  \
            cp_async16(s_ + OFF_AHI + so, arow_hi + k0_ + ch * 8, abytes);        \
            cp_async16(s_ + OFF_ALO + so, arow_lo + k0_ + ch * 8, abytes);        \
            cp_async16(s_ + OFF_BHI + so, brow_hi + k0_ + ch * 8, 16);            \
            cp_async16(s_ + OFF_BLO + so, brow_lo + k0_ + ch * 8, 16);            \
        }                                                                         \
        CP_COMMIT();                                                              \
    } while (0)

    // prime stages 0,1
    LOAD_STAGE(0, 0);
    if (NT > 1) LOAD_STAGE(1, 1);

    int stg = 0;
    for (int kt = 0; kt < NT; kt++) {
        // issue the load 2 tiles ahead (into the stage freed last iteration)
        if (kt + 2 < NT) {
            int ns = stg + 2; if (ns >= 3) ns -= 3;
            LOAD_STAGE(ns, kt + 2);
            CP_WAIT(2);
        } else if (kt + 1 < NT) {
            CP_WAIT(1);
        } else {
            CP_WAIT(0);
        }
        __syncthreads();

        uint32_t s0 = sb + (uint32_t)stg * STAGE_BYTES;
        #pragma unroll
        for (int kk = 0; kk < 4; kk++) {
            uint32_t ah[4][4], al[4][4], bh[2][4], bl[2][4];
            #pragma unroll
            for (int i = 0; i < 4; i++) {
                uint32_t ro = (uint32_t)((a_row + i * 16) * 128);
                uint32_t addr = s0 + OFF_AHI + ro + ((a_c + kk * 32) ^ asw);
                ldsm_x4(ah[i], addr);
                ldsm_x4(al[i], addr + (OFF_ALO - OFF_AHI));
            }
            #pragma unroll
            for (int p = 0; p < 2; p++) {
                uint32_t ro = (uint32_t)((b_row + p * 16) * 128);
                uint32_t addr = s0 + OFF_BHI + ro + ((b_c + kk * 32) ^ bsw);
                ldsm_x4(bh[p], addr);
                ldsm_x4(bl[p], addr + (OFF_BLO - OFF_BHI));
            }
            #pragma unroll
            for (int i = 0; i < 4; i++)
                #pragma unroll
                for (int j = 0; j < 4; j++) {
                    const uint32_t* bhj = &bh[j >> 1][(j & 1) * 2];
                    const uint32_t* blj = &bl[j >> 1][(j & 1) * 2];
                    mma_bf16(acc[i][j], ah[i], bhj);
                    mma_bf16(acc[i][j], ah[i], blj);
                    mma_bf16(acc[i][j], al[i], bhj);
                }
        }
        __syncthreads();
        stg = (stg == 2) ? 0 : stg + 1;
    }
    #undef LOAD_STAGE

    // -------- epilogue --------
    int g = lane >> 2;
    int cg = (lane & 3) * 2;
    #pragma unroll
    for (int i = 0; i < 4; i++) {
        #pragma unroll
        for (int half = 0; half < 2; half++) {
            int m = m0 + wm * 64 + i * 16 + g + half * 8;
            if (m < cnt) {
                int slot = base + m;
                float gate = (MODE == 1) ? g_gates[slot] : 0.f;
                #pragma unroll
                for (int j = 0; j < 4; j++) {
                    int col = n0 + wn * 32 + j * 8 + cg;
                    float bv0 = bias[(size_t)e * NTOT + col];
                    float bv1 = bias[(size_t)e * NTOT + col + 1];
                    float v0 = acc[i][j][half * 2 + 0] + bv0;
                    float v1 = acc[i][j][half * 2 + 1] + bv1;
                    if (MODE == 0) {
                        v0 = fmaxf(v0, 0.f); v1 = fmaxf(v1, 0.f);
                        __nv_bfloat16 h0 = __float2bfloat16(v0);
                        __nv_bfloat16 h1 = __float2bfloat16(v1);
                        __nv_bfloat16 l0 = __float2bfloat16(v0 - __bfloat162float(h0));
                        __nv_bfloat16 l1 = __float2bfloat16(v1 - __bfloat162float(h1));
                        __nv_bfloat162 hh = __halves2bfloat162(h0, h1);
                        __nv_bfloat162 ll = __halves2bfloat162(l0, l1);
                        *(uint32_t*)&g_h_hi[(size_t)slot * H + col] = *(uint32_t*)&hh;
                        *(uint32_t*)&g_h_lo[(size_t)slot * H + col] = *(uint32_t*)&ll;
                    } else {
                        float2 v = make_float2(gate * v0, gate * v1);
                        *(float2*)&g_eo[(size_t)slot * O + col] = v;
                    }
                }
            }
        }
    }
}

// ---------------- task towers ----------------
__global__ __launch_bounds__(256) void k_tower(
    const float* __restrict__ tw1, const float* __restrict__ tb1,
    const float* __restrict__ tw2, const float* __restrict__ tb2,
    float* __restrict__ out)
{
    int b0 = blockIdx.x * 16;
    int tid = threadIdx.x;
    int lane = tid & 31, wid = tid >> 5;

    __shared__ float moe_sh[16][O];
    __shared__ float sred[16][8];

    #pragma unroll
    for (int r = 0; r < 16; r++) {
        int b = b0 + r;
        int s0 = g_pair[b * 2 + 0], s1 = g_pair[b * 2 + 1];
        for (int c = tid; c < O; c += 256)
            moe_sh[r][c] = g_eo[(size_t)s0 * O + c] + g_eo[(size_t)s1 * O + c];
    }
    __syncthreads();

    for (int t = 0; t < T; t++) {
        float acc[16];
        #pragma unroll
        for (int r = 0; r < 16; r++) acc[r] = 0.f;

        const float* w1 = tw1 + (size_t)t * O * TH + tid;
        for (int o = 0; o < O; o++) {
            float w = w1[(size_t)o * TH];
            #pragma unroll
            for (int r = 0; r < 16; r++) acc[r] += moe_sh[r][o] * w;
        }
        float bb = tb1[t * TH + tid];
        float w2 = tw2[t * TH + tid];

        #pragma unroll
        for (int r = 0; r < 16; r++) {
            float th = fmaxf(acc[r] + bb, 0.f);
            float v = th * w2;
            for (int off = 16; off; off >>= 1)
                v += __shfl_down_sync(0xffffffffu, v, off);
            if (lane == 0) sred[r][wid] = v;
        }
        __syncthreads();
        if (tid < 16) {
            float s = 0.f;
            #pragma unroll
            for (int w = 0; w < 8; w++) s += sred[tid][w];
            out[(b0 + tid) * T + t] = s + tb2[t];
        }
        __syncthreads();
    }
}

// ---------------- launch ----------------
extern "C" void kernel_launch(void* const* d_in, const int* in_sizes, int n_in,
                              void* d_out, int out_size)
{
    const float* x     = (const float*)d_in[0];
    const float* plew  = (const float*)d_in[1];
    const float* pleb  = (const float*)d_in[2];
    const float* embW  = (const float*)d_in[3];
    const float* embb  = (const float*)d_in[4];
    const float* gW    = (const float*)d_in[5];
    const float* gb    = (const float*)d_in[6];
    const float* eW1   = (const float*)d_in[7];
    const float* eb1   = (const float*)d_in[8];
    const float* eW2   = (const float*)d_in[9];
    const float* eb2   = (const float*)d_in[10];
    const float* tw1   = (const float*)d_in[11];
    const float* tb1   = (const float*)d_in[12];
    const float* tw2   = (const float*)d_in[13];
    const float* tb2   = (const float*)d_in[14];
    float* out = (float*)d_out;

    const int SMEM_BYTES = 3 * STAGE_BYTES;   // 196608
    static bool attr_done = false;
    if (!attr_done) {
        cudaFuncSetAttribute(k_mma_gemm<F, H, 0>, cudaFuncAttributeMaxDynamicSharedMemorySize, SMEM_BYTES);
        cudaFuncSetAttribute(k_mma_gemm<H, O, 1>, cudaFuncAttributeMaxDynamicSharedMemorySize, SMEM_BYTES);
        attr_done = true;
    }

    __nv_bfloat16 *w1t_hi, *w1t_lo, *w2t_hi, *w2t_lo, *flat_hi, *flat_lo, *h_hi, *h_lo;
    cudaGetSymbolAddress((void**)&w1t_hi, g_w1t_hi);
    cudaGetSymbolAddress((void**)&w1t_lo, g_w1t_lo);
    cudaGetSymbolAddress((void**)&w2t_hi, g_w2t_hi);
    cudaGetSymbolAddress((void**)&w2t_lo, g_w2t_lo);
    cudaGetSymbolAddress((void**)&flat_hi, g_flat_hi);
    cudaGetSymbolAddress((void**)&flat_lo, g_flat_lo);
    cudaGetSymbolAddress((void**)&h_hi, g_h_hi);
    cudaGetSymbolAddress((void**)&h_lo, g_h_lo);

    k_init<<<1, 32>>>();
    k_wsplit<<<dim3(H / 32, F / 32, E), dim3(32, 8)>>>(eW1, w1t_hi, w1t_lo, F, H);
    k_wsplit<<<dim3(O / 32, H / 32, E), dim3(32, 8)>>>(eW2, w2t_hi, w2t_lo, H, O);
    k_ple<<<dim3(NF, B / 64), 256>>>(x, plew, pleb, embW, embb);
    k_gate<<<B, 256>>>(gW, gb);
    k_scan<<<1, 32>>>();
    k_assign<<<(B + 255) / 256, 256>>>();

    k_mma_gemm<F, H, 0><<<dim3(H / 128, B / GBM, E), 256, SMEM_BYTES>>>(
        flat_hi, flat_lo, w1t_hi, w1t_lo, eb1);
    k_mma_gemm<H, O, 1><<<dim3(O / 128, B / GBM, E), 256, SMEM_BYTES>>>(
        h_hi, h_lo, w2t_hi, w2t_lo, eb2);

    k_tower<<<B / 16, 256>>>(tw1, tb1, tw2, tb2, out);
}